// round 13
// baseline (speedup 1.0000x reference)
#include <cuda_runtime.h>
#include <cuda_bf16.h>
#include <math.h>
#include <stdint.h>

#define TOKENS 8192
#define DIM    4096
#define NEXP   256
#define TOPK   8

#define TM   64
#define BK   32                 // 2 x k16 per chunk
#define NCH  (DIM / BK)         // 128
#define NTH  512

#define ROWB   256              // 8 granules of 32B; granules 0..5 used
#define NROWS  (TM + NEXP)      // 320
#define STAGE  (NROWS * ROWB)   // 81920
#define SMEM_BYTES (2 * STAGE)  // 163840
#define LGS  264

// pre-split W: [c][n][6 granules x 32B]; granule j = sp*2+cq, words perm (P0,P4,P1,P5,P2,P6,P3,P7)
__device__ __align__(16) char g_ws[NCH * NEXP * 192];

__device__ __forceinline__ void mma_bf16(float* d,
                                         uint32_t a0, uint32_t a1, uint32_t a2, uint32_t a3,
                                         uint32_t b0, uint32_t b1) {
    asm volatile(
        "mma.sync.aligned.m16n8k16.row.col.f32.bf16.bf16.f32 "
        "{%0,%1,%2,%3},{%4,%5,%6,%7},{%8,%9},{%0,%1,%2,%3};"
        : "+f"(d[0]), "+f"(d[1]), "+f"(d[2]), "+f"(d[3])
        : "r"(a0), "r"(a1), "r"(a2), "r"(a3), "r"(b0), "r"(b1));
}

__device__ __forceinline__ uint32_t smem_u32(const void* p) {
    uint32_t a;
    asm("{ .reg .u64 t; cvta.to.shared.u64 t, %1; cvt.u32.u64 %0, t; }" : "=r"(a) : "l"(p));
    return a;
}
#define CP_ASYNC16(dst, src) \
    asm volatile("cp.async.cg.shared.global [%0], [%1], 16;" :: "r"(dst), "l"(src))
#define CP_COMMIT() asm volatile("cp.async.commit_group;" ::: "memory")
#define CP_WAIT0()  asm volatile("cp.async.wait_group 0;" ::: "memory")

// EXACT truncation 3-way split: v = h + m + l bit-exactly
__device__ __forceinline__ void tsplit3(float v, float* h, float* m, float* l) {
    float hh = __uint_as_float(__float_as_uint(v) & 0xFFFF0000u);
    float r  = v - hh;
    float mm = __uint_as_float(__float_as_uint(r) & 0xFFFF0000u);
    *h = hh; *m = mm; *l = r - mm;
}
__device__ __forceinline__ uint32_t packhi(float a, float b) {
    return __byte_perm(__float_as_uint(a), __float_as_uint(b), 0x7632);
}

// XLA logistic: 0.5 + 0.5 * tanh(0.5x)
__device__ __forceinline__ float xla_sigmoid(float v) {
    float x = 0.5f * v;
    float t;
    if (fabsf(x) < 0.0004f) {
        t = x;
    } else {
        float xc = fminf(fmaxf(x, -7.90531110763549805f), 7.90531110763549805f);
        float x2 = xc * xc;
        float p = -2.76076847742355e-16f;
        p = fmaf(p, x2, 2.00018790482477e-13f);
        p = fmaf(p, x2, -8.60467152213735e-11f);
        p = fmaf(p, x2, 5.12229709037114e-08f);
        p = fmaf(p, x2, 1.48572235717979e-05f);
        p = fmaf(p, x2, 6.37261928875436e-04f);
        p = fmaf(p, x2, 4.89352455891786e-03f);
        p = xc * p;
        float q = 1.19825839466702e-06f;
        q = fmaf(q, x2, 1.18534705686654e-04f);
        q = fmaf(q, x2, 2.26843463243900e-03f);
        q = fmaf(q, x2, 4.89352518554385e-03f);
        t = p / q;
    }
    return fmaf(0.5f, t, 0.5f);
}

// ============================================================================
// W prepass (identical numerics/layout to R9)
// ============================================================================
__global__ __launch_bounds__(256) void wsplit_kernel(const float* __restrict__ w) {
    int j = blockIdx.x * 256 + threadIdx.x;   // 32768 = n*128 + c
    int c = j & 127;
    int n = j >> 7;
    const float4* src = (const float4*)(w + (size_t)n * DIM + c * BK);
    float v[32];
    #pragma unroll
    for (int i = 0; i < 8; ++i) {
        float4 f = src[i];
        v[i*4+0] = f.x; v[i*4+1] = f.y; v[i*4+2] = f.z; v[i*4+3] = f.w;
    }
    float H[32], M[32], L[32];
    #pragma unroll
    for (int i = 0; i < 32; ++i) tsplit3(v[i], &H[i], &M[i], &L[i]);

    uint32_t* dst = (uint32_t*)(g_ws + ((size_t)c * NEXP + n) * 192);
    const int perm[8] = {0, 4, 1, 5, 2, 6, 3, 7};
    #pragma unroll
    for (int sp = 0; sp < 3; ++sp) {
        const float* S = (sp == 0) ? H : (sp == 1) ? M : L;
        #pragma unroll
        for (int cq = 0; cq < 2; ++cq) {
            #pragma unroll
            for (int wpos = 0; wpos < 8; ++wpos) {
                int pj = perm[wpos];
                int k0 = cq * 16 + 2 * pj;
                dst[(sp * 2 + cq) * 8 + wpos] = packhi(S[k0], S[k0 + 1]);
            }
        }
    }
}

// ============================================================================
// main kernel: bf16 6-term, register-dieted addressing
// ============================================================================
__global__ __launch_bounds__(NTH, 1)
void gate_bf16x3_kernel(const float* __restrict__ x,
                        float* __restrict__ out,
                        int write_idx)
{
    extern __shared__ char smem[];
    const uint32_t sb = smem_u32(smem);
    const int tid    = threadIdx.x;
    const int lane   = tid & 31;
    const int wid    = tid >> 5;
    const int warp_m = wid & 1;      // 2 x 32 tokens
    const int warp_n = wid >> 1;     // 8 x 32 experts
    const int t0     = blockIdx.x * TM;
    const int fr     = lane >> 2;
    const int fc     = lane & 3;
    const int rx     = fr & 3;       // shared row-xor for ALL A and B fragment rows

    float am[2][4][4], ac[2][4][4];
    #pragma unroll
    for (int tm = 0; tm < 2; ++tm)
        #pragma unroll
        for (int tn = 0; tn < 4; ++tn)
            #pragma unroll
            for (int q = 0; q < 4; ++q) { am[tm][tn][q] = 0.f; ac[tm][tn][q] = 0.f; }

    // granule offsets (shared by A and B fragment loads): 6 regs
    uint32_t goff[6];
    #pragma unroll
    for (int g = 0; g < 6; ++g) goff[g] = (uint32_t)((g ^ rx) * 32);

    // ---- W staging: thread = (row wn, half whf): 6 contiguous 16B units ----
    const int wn  = tid >> 1;          // 0..255
    const int whf = tid & 1;
    const char* wptr = g_ws + (size_t)wn * 192 + whf * 96;
    const int wrx = wn & 3;
    uint32_t wdst[3];
    #pragma unroll
    for (int k = 0; k < 3; ++k) {
        int g = whf * 3 + k;
        wdst[k] = (uint32_t)((TM + wn) * ROWB + ((g ^ wrx) * 32));
    }

    // ---- x staging: thread -> row xr = tid>>3, q = tid&7 (4 k-values at q*4) ----
    const int xr  = tid >> 3;
    const int xq  = tid & 7;
    const int xcq = xq >> 2;
    const int xj0 = (xq & 3) * 2;
    const int xp0 = (xj0 & 3) * 2 + (xj0 >> 2);
    const int xp1 = ((xj0 + 1) & 3) * 2 + ((xj0 + 1) >> 2);
    const float* xsrc = x + (size_t)(t0 + xr) * DIM + xq * 4;

    float4 ra;

    auto issue = [&](int c, int s) {
        const uint32_t sbase = sb + (uint32_t)(s * STAGE);
        const char* wsrc = wptr + (size_t)c * (NEXP * 192);
        #pragma unroll
        for (int k = 0; k < 3; ++k) {
            CP_ASYNC16(sbase + wdst[k],      (const void*)(wsrc + k * 32));
            CP_ASYNC16(sbase + wdst[k] + 16, (const void*)(wsrc + k * 32 + 16));
        }
        CP_COMMIT();
        ra = *(const float4*)(xsrc + (size_t)c * BK);
    };

    auto finish_x = [&](int s) {
        float H[4], M[4], L[4];
        tsplit3(ra.x, &H[0], &M[0], &L[0]);
        tsplit3(ra.y, &H[1], &M[1], &L[1]);
        tsplit3(ra.z, &H[2], &M[2], &L[2]);
        tsplit3(ra.w, &H[3], &M[3], &L[3]);
        uint32_t* base = (uint32_t*)(smem + s * STAGE + xr * ROWB);
        const int xrx = xr & 3;
        #pragma unroll
        for (int sp = 0; sp < 3; ++sp) {
            const float* S = (sp == 0) ? H : (sp == 1) ? M : L;
            uint32_t* g = base + (((sp * 2 + xcq) ^ xrx) * 8);
            g[xp0] = packhi(S[0], S[1]);
            g[xp1] = packhi(S[2], S[3]);
        }
    };

    // prologue
    issue(0, 0);
    finish_x(0);
    CP_WAIT0();
    __syncthreads();

    for (int c = 0; c < NCH; ++c) {
        const int s = c & 1;
        if (c + 1 < NCH) issue(c + 1, s ^ 1);

        const char* st = smem + s * STAGE;
        const char* aB = st + (warp_m * 32 + fr) * ROWB + fc * 8;
        const char* bB = st + (TM + warp_n * 32 + fr) * ROWB + fc * 8;

        #pragma unroll
        for (int cq = 0; cq < 2; ++cq) {
            uint2 A[3][2][2];   // [sp][tm][hf]
            #pragma unroll
            for (int sp = 0; sp < 3; ++sp) {
                const char* pa = aB + goff[sp * 2 + cq];
                #pragma unroll
                for (int tm = 0; tm < 2; ++tm)
                    #pragma unroll
                    for (int hf = 0; hf < 2; ++hf)
                        A[sp][tm][hf] = *(const uint2*)(pa + tm * (16 * ROWB) + hf * (8 * ROWB));
            }
            #pragma unroll
            for (int tn = 0; tn < 4; ++tn) {
                const char* pb = bB + tn * (8 * ROWB);
                uint2 bh = *(const uint2*)(pb + goff[cq]);
                uint2 bm = *(const uint2*)(pb + goff[2 + cq]);
                uint2 bl = *(const uint2*)(pb + goff[4 + cq]);
                #pragma unroll
                for (int tm = 0; tm < 2; ++tm) {
                    float* dm = am[tm][tn];
                    float* dc = ac[tm][tn];
                    uint2 ah0 = A[0][tm][0], ah1 = A[0][tm][1];
                    uint2 am0 = A[1][tm][0], am1 = A[1][tm][1];
                    uint2 al0 = A[2][tm][0], al1 = A[2][tm][1];
                    mma_bf16(dm, ah0.x, ah1.x, ah0.y, ah1.y, bh.x, bh.y);  // hh
                    mma_bf16(dc, ah0.x, ah1.x, ah0.y, ah1.y, bm.x, bm.y);  // hm
                    mma_bf16(dc, am0.x, am1.x, am0.y, am1.y, bh.x, bh.y);  // mh
                    mma_bf16(dc, am0.x, am1.x, am0.y, am1.y, bm.x, bm.y);  // mm
                    mma_bf16(dc, ah0.x, ah1.x, ah0.y, ah1.y, bl.x, bl.y);  // hl
                    mma_bf16(dc, al0.x, al1.x, al0.y, al1.y, bh.x, bh.y);  // lh
                }
            }
        }

        if (c + 1 < NCH) finish_x(s ^ 1);
        CP_WAIT0();
        __syncthreads();
    }

    // epilogue: logits -> smem [64][LGS]
    float* lg = (float*)smem;
    #pragma unroll
    for (int tm = 0; tm < 2; ++tm) {
        int r = warp_m * 32 + tm * 16 + fr;
        #pragma unroll
        for (int tn = 0; tn < 4; ++tn) {
            int cc = warp_n * 32 + tn * 8 + fc * 2;
            float v0 = am[tm][tn][0] + ac[tm][tn][0];
            float v1 = am[tm][tn][1] + ac[tm][tn][1];
            float v2 = am[tm][tn][2] + ac[tm][tn][2];
            float v3 = am[tm][tn][3] + ac[tm][tn][3];
            *(float2*)(lg + (size_t)r * LGS + cc)       = make_float2(v0, v1);
            *(float2*)(lg + (size_t)(r + 8) * LGS + cc) = make_float2(v2, v3);
        }
    }
    __syncthreads();

    // top-8 on sigmoid scores, lower-index tie-break
    #pragma unroll
    for (int it = 0; it < 4; ++it) {
        const int t = wid * 4 + it;
        float v[8];
        #pragma unroll
        for (int j = 0; j < 8; ++j)
            v[j] = xla_sigmoid(lg[(size_t)t * LGS + lane + j * 32]);

        float topv[8];
        int   topi[8];
        unsigned used = 0;

        #pragma unroll
        for (int r = 0; r < 8; ++r) {
            float best = -INFINITY;
            int   bidx = 0x7fffffff;
            #pragma unroll
            for (int j = 0; j < 8; ++j) {
                if (!((used >> j) & 1u)) {
                    float val = v[j];
                    int   id  = lane + j * 32;
                    if (val > best || (val == best && id < bidx)) { best = val; bidx = id; }
                }
            }
            #pragma unroll
            for (int off = 16; off > 0; off >>= 1) {
                float ov = __shfl_xor_sync(0xffffffffu, best, off);
                int   oi = __shfl_xor_sync(0xffffffffu, bidx, off);
                if (ov > best || (ov == best && oi < bidx)) { best = ov; bidx = oi; }
            }
            topv[r] = best;
            topi[r] = bidx;
            if ((bidx & 31) == lane) used |= 1u << (bidx >> 5);
        }

        float sum = 0.f;
        #pragma unroll
        for (int r = 0; r < 8; ++r) sum += topv[r];
        float inv = 1.f / sum;

        if (lane == 0) {
            int gt = t0 + t;
            #pragma unroll
            for (int r = 0; r < 8; ++r)
                out[(size_t)gt * TOPK + r] = topv[r] * inv;
            if (write_idx) {
                #pragma unroll
                for (int r = 0; r < 8; ++r)
                    out[(size_t)TOKENS * TOPK + (size_t)gt * TOPK + r] = (float)topi[r];
            }
        }
    }
}

extern "C" void kernel_launch(void* const* d_in, const int* in_sizes, int n_in,
                              void* d_out, int out_size)
{
    const float* x = (const float*)d_in[0];   // [TOKENS, DIM]
    const float* w = (const float*)d_in[1];   // [NEXP, DIM]
    float* out = (float*)d_out;

    int write_idx = (out_size >= 2 * TOKENS * TOPK) ? 1 : 0;

    cudaFuncSetAttribute(gate_bf16x3_kernel, cudaFuncAttributeMaxDynamicSharedMemorySize, SMEM_BYTES);

    wsplit_kernel<<<(NEXP * NCH) / 256, 256>>>(w);
    gate_bf16x3_kernel<<<TOKENS / TM, NTH, SMEM_BYTES>>>(x, out, write_idx);
}

// round 14
// speedup vs baseline: 1.2447x; 1.2447x over previous
#include <cuda_runtime.h>
#include <cuda_bf16.h>
#include <math.h>
#include <stdint.h>

#define TOKENS 8192
#define DIM    4096
#define NEXP   256
#define TOPK   8

#define TM   64
#define BK   32                 // 2 x k16 per chunk
#define NCH  (DIM / BK)         // 128
#define NTH  512

#define ROWB   256              // 8 granules of 32B; granules 0..5 used
#define STAGE  (320 * ROWB)     // rows 0..63 = A, 64..319 = B  (81920 B)
#define SMEM_BYTES (2 * STAGE)  // 163840
#define LGS  264

// pre-split W: [c][n][6 granules x 32B]; granule g = sp*2+cq, words perm (P0,P4,P1,P5,P2,P6,P3,P7)
__device__ __align__(16) char g_ws[NCH * NEXP * 192];
// pre-split X: [t][c][6 granules x 32B]
__device__ __align__(16) char g_xs[(size_t)TOKENS * NCH * 192];

__device__ __forceinline__ void mma_bf16(float* d,
                                         uint32_t a0, uint32_t a1, uint32_t a2, uint32_t a3,
                                         uint32_t b0, uint32_t b1) {
    asm volatile(
        "mma.sync.aligned.m16n8k16.row.col.f32.bf16.bf16.f32 "
        "{%0,%1,%2,%3},{%4,%5,%6,%7},{%8,%9},{%0,%1,%2,%3};"
        : "+f"(d[0]), "+f"(d[1]), "+f"(d[2]), "+f"(d[3])
        : "r"(a0), "r"(a1), "r"(a2), "r"(a3), "r"(b0), "r"(b1));
}

__device__ __forceinline__ uint32_t smem_u32(const void* p) {
    uint32_t a;
    asm("{ .reg .u64 t; cvta.to.shared.u64 t, %1; cvt.u32.u64 %0, t; }" : "=r"(a) : "l"(p));
    return a;
}
#define CP_ASYNC16(dst, src) \
    asm volatile("cp.async.cg.shared.global [%0], [%1], 16;" :: "r"(dst), "l"(src))
#define CP_COMMIT() asm volatile("cp.async.commit_group;" ::: "memory")
#define CP_WAIT0()  asm volatile("cp.async.wait_group 0;" ::: "memory")

// EXACT truncation 3-way split: v = h + m + l bit-exactly
__device__ __forceinline__ void tsplit3(float v, float* h, float* m, float* l) {
    float hh = __uint_as_float(__float_as_uint(v) & 0xFFFF0000u);
    float r  = v - hh;
    float mm = __uint_as_float(__float_as_uint(r) & 0xFFFF0000u);
    *h = hh; *m = mm; *l = r - mm;
}
__device__ __forceinline__ uint32_t packhi(float a, float b) {
    return __byte_perm(__float_as_uint(a), __float_as_uint(b), 0x7632);
}

// XLA logistic: 0.5 + 0.5 * tanh(0.5x)
__device__ __forceinline__ float xla_sigmoid(float v) {
    float x = 0.5f * v;
    float t;
    if (fabsf(x) < 0.0004f) {
        t = x;
    } else {
        float xc = fminf(fmaxf(x, -7.90531110763549805f), 7.90531110763549805f);
        float x2 = xc * xc;
        float p = -2.76076847742355e-16f;
        p = fmaf(p, x2, 2.00018790482477e-13f);
        p = fmaf(p, x2, -8.60467152213735e-11f);
        p = fmaf(p, x2, 5.12229709037114e-08f);
        p = fmaf(p, x2, 1.48572235717979e-05f);
        p = fmaf(p, x2, 6.37261928875436e-04f);
        p = fmaf(p, x2, 4.89352455891786e-03f);
        p = xc * p;
        float q = 1.19825839466702e-06f;
        q = fmaf(q, x2, 1.18534705686654e-04f);
        q = fmaf(q, x2, 2.26843463243900e-03f);
        q = fmaf(q, x2, 4.89352518554385e-03f);
        t = p / q;
    }
    return fmaf(0.5f, t, 0.5f);
}

// ============================================================================
// W prepass (8us, measured)
// ============================================================================
__global__ __launch_bounds__(256) void wsplit_kernel(const float* __restrict__ w) {
    int j = blockIdx.x * 256 + threadIdx.x;   // 32768 = n*128 + c
    int c = j & 127;
    int n = j >> 7;
    const float4* src = (const float4*)(w + (size_t)n * DIM + c * BK);
    float v[32];
    #pragma unroll
    for (int i = 0; i < 8; ++i) {
        float4 f = src[i];
        v[i*4+0] = f.x; v[i*4+1] = f.y; v[i*4+2] = f.z; v[i*4+3] = f.w;
    }
    float H[32], M[32], L[32];
    #pragma unroll
    for (int i = 0; i < 32; ++i) tsplit3(v[i], &H[i], &M[i], &L[i]);

    uint32_t* dst = (uint32_t*)(g_ws + ((size_t)c * NEXP + n) * 192);
    const int perm[8] = {0, 4, 1, 5, 2, 6, 3, 7};
    #pragma unroll
    for (int sp = 0; sp < 3; ++sp) {
        const float* S = (sp == 0) ? H : (sp == 1) ? M : L;
        #pragma unroll
        for (int cq = 0; cq < 2; ++cq) {
            #pragma unroll
            for (int wpos = 0; wpos < 8; ++wpos) {
                int pj = perm[wpos];
                int k0 = cq * 16 + 2 * pj;
                dst[(sp * 2 + cq) * 8 + wpos] = packhi(S[k0], S[k0 + 1]);
            }
        }
    }
}

// ============================================================================
// X prepass v3: coalesced load, smem-staged permute, coalesced uint4 writeout
// block 256 thr handles 32 tc-blocks; grid = 1048576/32 = 32768
// ============================================================================
__global__ __launch_bounds__(256) void xsplit_kernel(const float* __restrict__ x) {
    __shared__ uint32_t sbuf[32 * 48];   // 6 KB
    const int tid = threadIdx.x;
    const size_t tcbase = (size_t)blockIdx.x * 32;

    // load one float4 per thread (coalesced), split, stage
    {
        const int tc = tid >> 3;       // 0..31
        const int q  = tid & 7;        // float4 index within 32 values
        float4 f = *(const float4*)(x + (tcbase + tc) * 32 + q * 4);
        float H[4], M[4], L[4];
        tsplit3(f.x, &H[0], &M[0], &L[0]);
        tsplit3(f.y, &H[1], &M[1], &L[1]);
        tsplit3(f.z, &H[2], &M[2], &L[2]);
        tsplit3(f.w, &H[3], &M[3], &L[3]);
        const int cq = q >> 2;
        const int j0 = (q & 3) * 2;
        const int w0 = (j0 & 3) * 2 + (j0 >> 2);
        const int w1 = ((j0 + 1) & 3) * 2 + ((j0 + 1) >> 2);
        uint32_t* base = sbuf + tc * 48;
        #pragma unroll
        for (int sp = 0; sp < 3; ++sp) {
            const float* S = (sp == 0) ? H : (sp == 1) ? M : L;
            uint32_t* g = base + (sp * 2 + cq) * 8;
            g[w0] = packhi(S[0], S[1]);
            g[w1] = packhi(S[2], S[3]);
        }
    }
    __syncthreads();

    // writeout: 32*192B = 6144B = 384 uint4, fully coalesced
    uint4* dst = (uint4*)(g_xs + tcbase * 192);
    const uint4* srcs = (const uint4*)sbuf;
    dst[tid] = srcs[tid];
    if (tid < 128) dst[256 + tid] = srcs[256 + tid];
}

// ============================================================================
// main kernel: pure cp.async + LDS + MMA (R7 verbatim — measured 245us)
// ============================================================================
__global__ __launch_bounds__(NTH, 1)
void gate_bf16x3_kernel(float* __restrict__ out, int write_idx)
{
    extern __shared__ char smem[];
    const uint32_t sb = smem_u32(smem);
    const int tid    = threadIdx.x;
    const int lane   = tid & 31;
    const int wid    = tid >> 5;
    const int warp_m = wid & 1;
    const int warp_n = wid >> 1;
    const int t0     = blockIdx.x * TM;
    const int fr     = lane >> 2;
    const int fc     = lane & 3;

    float am[2][4][4], ac[2][4][4];
    #pragma unroll
    for (int tm = 0; tm < 2; ++tm)
        #pragma unroll
        for (int tn = 0; tn < 4; ++tn)
            #pragma unroll
            for (int q = 0; q < 4; ++q) { am[tm][tn][q] = 0.f; ac[tm][tn][q] = 0.f; }

    // precomputed staging addresses (R7 mapping — consecutive 16B units per warp)
    const int uA0  = tid;
    const int rA0  = uA0 / 12;
    const int mA0  = uA0 - rA0 * 12;
    const uint32_t dstA0 = (uint32_t)(rA0 * ROWB + (((mA0 >> 1) ^ (rA0 & 3)) * 32) + (mA0 & 1) * 16);
    const char* srcA0 = g_xs + (size_t)(t0 + rA0) * (NCH * 192) + mA0 * 16;

    const int uA1  = 512 + tid;
    const int rA1  = uA1 / 12;
    const int mA1  = uA1 - rA1 * 12;
    const uint32_t dstA1 = (uint32_t)(rA1 * ROWB + (((mA1 >> 1) ^ (rA1 & 3)) * 32) + (mA1 & 1) * 16);
    const char* srcA1 = g_xs + (size_t)(t0 + rA1) * (NCH * 192) + mA1 * 16;

    uint32_t dstB[6], srcB[6];
    #pragma unroll
    for (int i = 0; i < 6; ++i) {
        int u  = tid + 512 * i;
        int n  = u / 12;
        int mi = u - n * 12;
        int r  = 64 + n;
        dstB[i] = (uint32_t)(r * ROWB + (((mi >> 1) ^ (r & 3)) * 32) + (mi & 1) * 16);
        srcB[i] = (uint32_t)(n * 192 + mi * 16);
    }

    auto issue = [&](int c, int s) {
        const uint32_t sbase = sb + (uint32_t)(s * STAGE);
        const char* wb = g_ws + (size_t)c * (NEXP * 192);
        #pragma unroll
        for (int i = 0; i < 6; ++i)
            CP_ASYNC16(sbase + dstB[i], (const void*)(wb + srcB[i]));
        CP_ASYNC16(sbase + dstA0, (const void*)(srcA0 + (size_t)c * 192));
        if (tid < 256)
            CP_ASYNC16(sbase + dstA1, (const void*)(srcA1 + (size_t)c * 192));
        CP_COMMIT();
    };

    int arow[2][2];
    #pragma unroll
    for (int tm = 0; tm < 2; ++tm) {
        arow[tm][0] = warp_m * 32 + tm * 16 + fr;
        arow[tm][1] = arow[tm][0] + 8;
    }
    int brow[4];
    #pragma unroll
    for (int tn = 0; tn < 4; ++tn) brow[tn] = 64 + warp_n * 32 + tn * 8 + fr;

    issue(0, 0);
    CP_WAIT0();
    __syncthreads();

    for (int c = 0; c < NCH; ++c) {
        const int s = c & 1;
        if (c + 1 < NCH) issue(c + 1, s ^ 1);

        const char* st = smem + s * STAGE;
        #pragma unroll
        for (int cq = 0; cq < 2; ++cq) {
            uint2 A[3][2][2];
            #pragma unroll
            for (int tm = 0; tm < 2; ++tm)
                #pragma unroll
                for (int hf = 0; hf < 2; ++hf) {
                    int r = arow[tm][hf];
                    const char* pr = st + r * ROWB;
                    const int rx = r & 3;
                    A[0][tm][hf] = *(const uint2*)(pr + (((0 * 2 + cq) ^ rx) * 32) + fc * 8);
                    A[1][tm][hf] = *(const uint2*)(pr + (((1 * 2 + cq) ^ rx) * 32) + fc * 8);
                    A[2][tm][hf] = *(const uint2*)(pr + (((2 * 2 + cq) ^ rx) * 32) + fc * 8);
                }
            #pragma unroll
            for (int tn = 0; tn < 4; ++tn) {
                int r = brow[tn];
                const char* pr = st + r * ROWB;
                const int rx = r & 3;
                uint2 bh = *(const uint2*)(pr + (((0 * 2 + cq) ^ rx) * 32) + fc * 8);
                uint2 bm = *(const uint2*)(pr + (((1 * 2 + cq) ^ rx) * 32) + fc * 8);
                uint2 bl = *(const uint2*)(pr + (((2 * 2 + cq) ^ rx) * 32) + fc * 8);
                #pragma unroll
                for (int tm = 0; tm < 2; ++tm) {
                    float* dm = am[tm][tn];
                    float* dc = ac[tm][tn];
                    uint2 ah0 = A[0][tm][0], ah1 = A[0][tm][1];
                    uint2 am0 = A[1][tm][0], am1 = A[1][tm][1];
                    uint2 al0 = A[2][tm][0], al1 = A[2][tm][1];
                    mma_bf16(dm, ah0.x, ah1.x, ah0.y, ah1.y, bh.x, bh.y);  // hh
                    mma_bf16(dc, ah0.x, ah1.x, ah0.y, ah1.y, bm.x, bm.y);  // hm
                    mma_bf16(dc, am0.x, am1.x, am0.y, am1.y, bh.x, bh.y);  // mh
                    mma_bf16(dc, am0.x, am1.x, am0.y, am1.y, bm.x, bm.y);  // mm
                    mma_bf16(dc, ah0.x, ah1.x, ah0.y, ah1.y, bl.x, bl.y);  // hl
                    mma_bf16(dc, al0.x, al1.x, al0.y, al1.y, bh.x, bh.y);  // lh
                }
            }
        }

        CP_WAIT0();
        __syncthreads();
    }

    // epilogue: logits -> smem [64][LGS]
    float* lg = (float*)smem;
    #pragma unroll
    for (int tm = 0; tm < 2; ++tm) {
        int r = warp_m * 32 + tm * 16 + fr;
        #pragma unroll
        for (int tn = 0; tn < 4; ++tn) {
            int cc = warp_n * 32 + tn * 8 + fc * 2;
            float v0 = am[tm][tn][0] + ac[tm][tn][0];
            float v1 = am[tm][tn][1] + ac[tm][tn][1];
            float v2 = am[tm][tn][2] + ac[tm][tn][2];
            float v3 = am[tm][tn][3] + ac[tm][tn][3];
            *(float2*)(lg + (size_t)r * LGS + cc)       = make_float2(v0, v1);
            *(float2*)(lg + (size_t)(r + 8) * LGS + cc) = make_float2(v2, v3);
        }
    }
    __syncthreads();

    // top-8 on sigmoid scores, lower-index tie-break
    #pragma unroll
    for (int it = 0; it < 4; ++it) {
        const int t = wid * 4 + it;
        float v[8];
        #pragma unroll
        for (int j = 0; j < 8; ++j)
            v[j] = xla_sigmoid(lg[(size_t)t * LGS + lane + j * 32]);

        float topv[8];
        int   topi[8];
        unsigned used = 0;

        #pragma unroll
        for (int r = 0; r < 8; ++r) {
            float best = -INFINITY;
            int   bidx = 0x7fffffff;
            #pragma unroll
            for (int j = 0; j < 8; ++j) {
                if (!((used >> j) & 1u)) {
                    float val = v[j];
                    int   id  = lane + j * 32;
                    if (val > best || (val == best && id < bidx)) { best = val; bidx = id; }
                }
            }
            #pragma unroll
            for (int off = 16; off > 0; off >>= 1) {
                float ov = __shfl_xor_sync(0xffffffffu, best, off);
                int   oi = __shfl_xor_sync(0xffffffffu, bidx, off);
                if (ov > best || (ov == best && oi < bidx)) { best = ov; bidx = oi; }
            }
            topv[r] = best;
            topi[r] = bidx;
            if ((bidx & 31) == lane) used |= 1u << (bidx >> 5);
        }

        float sum = 0.f;
        #pragma unroll
        for (int r = 0; r < 8; ++r) sum += topv[r];
        float inv = 1.f / sum;

        if (lane == 0) {
            int gt = t0 + t;
            #pragma unroll
            for (int r = 0; r < 8; ++r)
                out[(size_t)gt * TOPK + r] = topv[r] * inv;
            if (write_idx) {
                #pragma unroll
                for (int r = 0; r < 8; ++r)
                    out[(size_t)TOKENS * TOPK + (size_t)gt * TOPK + r] = (float)topi[r];
            }
        }
    }
}

extern "C" void kernel_launch(void* const* d_in, const int* in_sizes, int n_in,
                              void* d_out, int out_size)
{
    const float* x = (const float*)d_in[0];   // [TOKENS, DIM]
    const float* w = (const float*)d_in[1];   // [NEXP, DIM]
    float* out = (float*)d_out;

    int write_idx = (out_size >= 2 * TOKENS * TOPK) ? 1 : 0;

    cudaFuncSetAttribute(gate_bf16x3_kernel, cudaFuncAttributeMaxDynamicSharedMemorySize, SMEM_BYTES);

    wsplit_kernel<<<(NEXP * NCH) / 256, 256>>>(w);
    xsplit_kernel<<<(TOKENS * NCH) / 32, 256>>>(x);
    gate_bf16x3_kernel<<<TOKENS / TM, NTH, SMEM_BYTES>>>(out, write_idx);
}